// round 16
// baseline (speedup 1.0000x reference)
#include <cuda_runtime.h>

#define P 16384
#define H 256
#define E 64
#define NA 64
#define PE (P*E)

// ---------------- static scratch ----------------
__device__ float g_tsum[H], g_tsumsq[H];     // temp BN sums
__device__ float g_ssum[H], g_ssumsq[H];     // spat BN sums
__device__ int   g_ticket;                   // last-block ticket for tstats+prep
__device__ float g_w2T[H*NA];                // BN-folded temporal weights, transposed [h][a]
__device__ float g_cA[NA];                   // folded bias for te
__device__ float g_c[P];                     // c[p] = b_spat . te[p]
__device__ float g_v[P*H];                   // v[p,h]
__device__ float g_Vg[P*4];                  // group sums of v
__device__ float g_D[P*H];                   // raw dots
__device__ float g_ss[H], g_tt[H];           // spat BN scale/shift
__device__ float g_attnT[E*P];               // attn transposed [E][P]
__device__ float g_wv[P*E];                  // softmax weights [P][E]
__device__ float g_pmax[E*4], g_psum[E*4];   // softmax partials (4 chunks per e)

// ---------------- init: zero accumulators + ticket ----------------
__global__ void k_init() {
    int i = threadIdx.x;
    g_tsum[i] = 0.f; g_tsumsq[i] = 0.f; g_ssum[i] = 0.f; g_ssumsq[i] = 0.f;
    if (i == 0) g_ticket = 0;
}

// ---------------- temp stats + (last block) BN weight folding ----------------
// stats: per-column sums. Last block to finish also computes
// w2T[h,a] = sc[h]*wt[a,h] and cA[a] = bt[a] + sum_h sh[h]*wt[a,h].
__global__ void k_tstats(const float* __restrict__ th,
                         const float* __restrict__ gamma,
                         const float* __restrict__ beta,
                         const float* __restrict__ wt,
                         const float* __restrict__ bt) {
    int c = threadIdx.x;
    float s = 0.f, s2 = 0.f;
    for (int p = blockIdx.x; p < P; p += gridDim.x) {
        float x = th[(size_t)p*H + c];
        s += x; s2 += x*x;
    }
    atomicAdd(&g_tsum[c], s);
    atomicAdd(&g_tsumsq[c], s2);
    __threadfence();

    __shared__ int s_last;
    __shared__ float s_sh[H];
    if (c == 0) {
        int t = atomicAdd(&g_ticket, 1);
        s_last = (t == (int)gridDim.x - 1);
    }
    __syncthreads();
    if (!s_last) return;

    // ---- prep (single block; all stats now complete) ----
    float m   = g_tsum[c]   * (1.0f/P);
    float var = g_tsumsq[c] * (1.0f/P) - m*m;
    float sc  = gamma[c] * rsqrtf(var + 1e-5f);
    float sh  = beta[c] - m*sc;
    s_sh[c] = sh;
    // w2T row h=c
    #pragma unroll
    for (int a = 0; a < NA; a += 4) {
        float4 o;
        o.x = sc * wt[(size_t)(a+0)*H + c];
        o.y = sc * wt[(size_t)(a+1)*H + c];
        o.z = sc * wt[(size_t)(a+2)*H + c];
        o.w = sc * wt[(size_t)(a+3)*H + c];
        *(float4*)&g_w2T[c*NA + a] = o;
    }
    __syncthreads();
    int w = c >> 5, lane = c & 31;
    for (int a = w; a < NA; a += 8) {
        float part = 0.f;
        for (int hh = lane; hh < H; hh += 32) part += s_sh[hh] * wt[(size_t)a*H + hh];
        #pragma unroll
        for (int o = 16; o; o >>= 1) part += __shfl_xor_sync(0xffffffffu, part, o);
        if (lane == 0) g_cA[a] = bt[a] + part;
    }
}

// ---------------- fused: te = th@w2^T + cA (smem) ; v = te@ws ; c, Vg ----------------
// 64 persons per block, 512 threads (R12-measured 51.7us)
__global__ void __launch_bounds__(512) k_tev(const float* __restrict__ th,
                                             const float* __restrict__ ws,
                                             const float* __restrict__ bs) {
    extern __shared__ float sm[];
    float* s_a  = sm;                  // [64][132] th chunk; later s_te [64][68]
    float* s_w  = sm + 64*132;         // [128][68] w2T chunk; later s_ws [64][132]
    float* s_c  = s_w + 128*68;        // [64]
    float* s_vg = s_c + 64;            // [64][4]
    int tid = threadIdx.x;
    int pbase = blockIdx.x * 64;

    if (tid < 64)  s_c[tid] = 0.f;
    if (tid < 256) s_vg[tid] = 0.f;
    __syncthreads();

    // ---- GEMM1: te[64p][64a] = th[64p][256h] @ w2T ----
    int ty = tid >> 4, tx = tid & 15;            // 32x16 -> 2p x 4a tile
    float acc[2][4] = {};
    int c4  = (tid & 31) * 4, r0  = tid >> 5;    // stagers for 128-wide chunks
    int c4a = (tid & 15) * 4, r0w = tid >> 4;    // stager for s_w [128][64]

    for (int kc = 0; kc < 256; kc += 128) {
        #pragma unroll
        for (int r = r0; r < 64; r += 16)
            *(float4*)&s_a[r*132 + c4] = *(const float4*)&th[(size_t)(pbase + r)*H + kc + c4];
        #pragma unroll
        for (int r = r0w; r < 128; r += 32)
            *(float4*)&s_w[r*68 + c4a] = *(const float4*)&g_w2T[(size_t)(kc + r)*NA + c4a];
        __syncthreads();
        #pragma unroll 8
        for (int k = 0; k < 128; k++) {
            float a0 = s_a[(ty*2+0)*132 + k];
            float a1 = s_a[(ty*2+1)*132 + k];
            float4 b = *(float4*)&s_w[k*68 + tx*4];
            acc[0][0] += a0*b.x; acc[0][1] += a0*b.y; acc[0][2] += a0*b.z; acc[0][3] += a0*b.w;
            acc[1][0] += a1*b.x; acc[1][1] += a1*b.y; acc[1][2] += a1*b.z; acc[1][3] += a1*b.w;
        }
        __syncthreads();
    }

    // te epilogue: add cA, write into s_te (reuse s_a), accumulate c[p]
    float* s_te = s_a;                 // [64][68]
    {
        float4 cA4 = *(const float4*)&g_cA[tx*4];
        float4 bs4 = *(const float4*)&bs[tx*4];
        #pragma unroll
        for (int i = 0; i < 2; i++) {
            int pl = ty*2 + i;
            float t0 = acc[i][0] + cA4.x;
            float t1 = acc[i][1] + cA4.y;
            float t2 = acc[i][2] + cA4.z;
            float t3 = acc[i][3] + cA4.w;
            s_te[pl*68 + tx*4 + 0] = t0;
            s_te[pl*68 + tx*4 + 1] = t1;
            s_te[pl*68 + tx*4 + 2] = t2;
            s_te[pl*68 + tx*4 + 3] = t3;
            atomicAdd(&s_c[pl], t0*bs4.x + t1*bs4.y + t2*bs4.z + t3*bs4.w);
        }
    }
    __syncthreads();

    // ---- GEMM2: v[64p][256h] = te[64p][64a] @ ws[64a][256h] ----
    float* s_ws = s_w;                 // [64][132]
    int ty2 = tid >> 5, tx2 = tid & 31;     // 16x32 -> 4p x 4h tile per chunk
    for (int hc = 0; hc < 256; hc += 128) {
        #pragma unroll
        for (int r = r0; r < 64; r += 16)
            *(float4*)&s_ws[r*132 + c4] = *(const float4*)&ws[(size_t)r*H + hc + c4];
        __syncthreads();
        float a2c[4][4] = {};
        #pragma unroll 8
        for (int a = 0; a < 64; a++) {
            float4 w = *(float4*)&s_ws[a*132 + tx2*4];
            #pragma unroll
            for (int i = 0; i < 4; i++) {
                float t = s_te[(ty2*4+i)*68 + a];
                a2c[i][0] += t*w.x; a2c[i][1] += t*w.y; a2c[i][2] += t*w.z; a2c[i][3] += t*w.w;
            }
        }
        int g = (hc + tx2*4) >> 6;
        #pragma unroll
        for (int i = 0; i < 4; i++) {
            int pl = ty2*4 + i;
            float4 o;
            o.x = a2c[i][0]; o.y = a2c[i][1]; o.z = a2c[i][2]; o.w = a2c[i][3];
            *(float4*)&g_v[(size_t)(pbase + pl)*H + hc + tx2*4] = o;
            atomicAdd(&s_vg[pl*4 + g], o.x + o.y + o.z + o.w);
        }
        __syncthreads();
    }

    if (tid < 256) g_Vg[(size_t)pbase*4 + tid] = s_vg[tid];
    if (tid < 64)  g_c[pbase + tid] = s_c[tid];
}

// ---------------- fused big pass 1: D[p,ch] dots + spat BN stats ----------------
__global__ void __launch_bounds__(256) k_pass1(const float* __restrict__ xg) {
    __shared__ float s_sum[H], s_sq[H];
    __shared__ __align__(16) float s_D[8][256];
    int tid = threadIdx.x;
    s_sum[tid] = 0.f; s_sq[tid] = 0.f;
    __syncthreads();

    int warp = tid >> 5, lane = tid & 31;
    int p = blockIdx.x * 8 + warp;
    int rr = lane >> 3, seg = lane & 7;

    float vreg[8];
    const float* vp = &g_v[(size_t)p*H + lane*8];
    #pragma unroll
    for (int i = 0; i < 8; i++) vreg[i] = vp[i];

    const float* xp = xg + (size_t)p*(H*E) + lane*8;

    #pragma unroll 4
    for (int it = 0; it < 64; it++) {
        float4 a = *(const float4*)(xp + it*256);
        float4 b = *(const float4*)(xp + it*256 + 4);
        float dot = a.x*vreg[0] + a.y*vreg[1] + a.z*vreg[2] + a.w*vreg[3]
                  + b.x*vreg[4] + b.y*vreg[5] + b.z*vreg[6] + b.w*vreg[7];
        float s1 = a.x + a.y + a.z + a.w + b.x + b.y + b.z + b.w;
        float s2 = a.x*a.x + a.y*a.y + a.z*a.z + a.w*a.w
                 + b.x*b.x + b.y*b.y + b.z*b.z + b.w*b.w;
        #pragma unroll
        for (int o = 1; o < 8; o <<= 1) {
            dot += __shfl_xor_sync(0xffffffffu, dot, o);
            s1  += __shfl_xor_sync(0xffffffffu, s1,  o);
            s2  += __shfl_xor_sync(0xffffffffu, s2,  o);
        }
        if (seg == 0) {
            int ch = it*4 + rr;
            s_D[warp][ch] = dot;
            atomicAdd(&s_sum[ch], s1);
            atomicAdd(&s_sq[ch],  s2);
        }
    }
    __syncwarp();
    float4 d0 = *(float4*)&s_D[warp][lane*4];
    float4 d1 = *(float4*)&s_D[warp][128 + lane*4];
    *(float4*)&g_D[(size_t)p*H + lane*4]       = d0;
    *(float4*)&g_D[(size_t)p*H + 128 + lane*4] = d1;

    __syncthreads();
    atomicAdd(&g_ssum[tid],   s_sum[tid]);
    atomicAdd(&g_ssumsq[tid], s_sq[tid]);
}

// ---------------- attn scores (BN finalize folded in; 4-way e-split) ----------------
__global__ void __launch_bounds__(256) k_attn(const float* __restrict__ gamma,
                                              const float* __restrict__ beta) {
    __shared__ __align__(16) float ss[H];
    __shared__ __align__(16) float tt[H];
    int tid = threadIdx.x;
    {
        float inv = 1.0f / (float)PE;
        float m   = g_ssum[tid] * inv;
        float var = g_ssumsq[tid] * inv - m*m;
        float s   = gamma[tid] * rsqrtf(var + 1e-5f);
        ss[tid] = s;
        tt[tid] = beta[tid] - m*s;
        if (blockIdx.x == 0) { g_ss[tid] = s; g_tt[tid] = tt[tid]; }
    }
    __syncthreads();

    int pb = blockIdx.x & 63, ec = blockIdx.x >> 6;
    int p = pb*256 + tid;
    float vg0 = g_Vg[p*4+0], vg1 = g_Vg[p*4+1], vg2 = g_Vg[p*4+2], vg3 = g_Vg[p*4+3];
    float cp = g_c[p];
    const float4* Dp = (const float4*)&g_D[(size_t)p*H];
    const float T = 8.0f;   // E / sqrt(A)
    #pragma unroll
    for (int e = ec*16; e < ec*16 + 16; e++) {
        float4 d = Dp[e];
        float4 s = *(float4*)&ss[e*4];
        float4 t = *(float4*)&tt[e*4];
        float val = s.x*d.x + s.y*d.y + s.z*d.z + s.w*d.w
                  + t.x*vg0 + t.y*vg1 + t.z*vg2 + t.w*vg3 + cp;
        g_attnT[(size_t)e*P + p] = T * val;
    }
}

// ---------------- softmax stage 1: per-(e,chunk) max + sumexp ----------------
__global__ void __launch_bounds__(256) k_sm1() {
    __shared__ float red[32];
    __shared__ float bmax;
    int tid = threadIdx.x;
    const float* row = &g_attnT[(size_t)(blockIdx.x >> 2)*P + (blockIdx.x & 3)*4096];

    float mx = -1e30f;
    for (int i = tid; i < 4096; i += 256) mx = fmaxf(mx, row[i]);
    #pragma unroll
    for (int o = 16; o; o >>= 1) mx = fmaxf(mx, __shfl_xor_sync(0xffffffffu, mx, o));
    if ((tid & 31) == 0) red[tid >> 5] = mx;
    __syncthreads();
    if (tid < 32) {
        float v = (tid < 8) ? red[tid] : -1e30f;
        #pragma unroll
        for (int o = 4; o; o >>= 1) v = fmaxf(v, __shfl_xor_sync(0xffffffffu, v, o));
        if (tid == 0) bmax = v;
    }
    __syncthreads();
    float m = bmax;

    float s = 0.f;
    for (int i = tid; i < 4096; i += 256) s += expf(row[i] - m);
    #pragma unroll
    for (int o = 16; o; o >>= 1) s += __shfl_xor_sync(0xffffffffu, s, o);
    if ((tid & 31) == 0) red[tid >> 5] = s;
    __syncthreads();
    if (tid < 32) {
        float v = (tid < 8) ? red[tid] : 0.f;
        #pragma unroll
        for (int o = 4; o; o >>= 1) v += __shfl_xor_sync(0xffffffffu, v, o);
        if (tid == 0) { g_pmax[blockIdx.x] = m; g_psum[blockIdx.x] = v; }
    }
}

// ---------------- normalize + transpose: wv[p][e] = exp(attnT-M)*invS ----------------
__global__ void __launch_bounds__(256) k_trn() {
    __shared__ float sM[64], sInv[64];
    __shared__ float stile[64][65];
    int p0 = blockIdx.x * 64, tid = threadIdx.x;
    if (tid < 64) {
        float m0 = g_pmax[tid*4+0], m1 = g_pmax[tid*4+1];
        float m2 = g_pmax[tid*4+2], m3 = g_pmax[tid*4+3];
        float M = fmaxf(fmaxf(m0, m1), fmaxf(m2, m3));
        float S = g_psum[tid*4+0]*expf(m0-M) + g_psum[tid*4+1]*expf(m1-M)
                + g_psum[tid*4+2]*expf(m2-M) + g_psum[tid*4+3]*expf(m3-M);
        sM[tid] = M; sInv[tid] = 1.0f / S;
    }
    __syncthreads();
    int er = tid >> 6, pc = tid & 63;
    #pragma unroll
    for (int ee = 0; ee < 64; ee += 4) {
        float a = g_attnT[(size_t)(ee + er)*P + p0 + pc];
        stile[ee + er][pc] = expf(a - sM[ee + er]) * sInv[ee + er];
    }
    __syncthreads();
    int pr = tid >> 6, ec = tid & 63;
    #pragma unroll
    for (int pp = 0; pp < 64; pp += 4)
        g_wv[(size_t)(p0 + pp + pr)*E + ec] = stile[ec][pp + pr];
}

// ---------------- final big pass 2: warp-per-person streaming ----------------
__global__ void __launch_bounds__(256) k_out(const float* __restrict__ xg,
                                             float* __restrict__ out) {
    __shared__ float s_ss[H], s_tt[H];
    __shared__ float scoef[8][260];
    __shared__ float scg[8][4];
    int tid = threadIdx.x, warp = tid >> 5, lane = tid & 31;
    s_ss[tid] = g_ss[tid];
    s_tt[tid] = g_tt[tid];
    __syncthreads();

    int p = blockIdx.x * 8 + warp;
    float wv0 = g_wv[(size_t)p*E + lane];
    float wv1 = g_wv[(size_t)p*E + 32 + lane];
    float cgp0 = 0.f, cgp1 = 0.f, cgp2 = 0.f, cgp3 = 0.f;
    #pragma unroll
    for (int g = 0; g < 4; g++) {
        scoef[warp][4*lane + g]      = wv0 * s_ss[4*lane + g];
        scoef[warp][4*(lane+32) + g] = wv1 * s_ss[4*(lane+32) + g];
    }
    cgp0 = wv0*s_tt[4*lane+0] + wv1*s_tt[4*(lane+32)+0];
    cgp1 = wv0*s_tt[4*lane+1] + wv1*s_tt[4*(lane+32)+1];
    cgp2 = wv0*s_tt[4*lane+2] + wv1*s_tt[4*(lane+32)+2];
    cgp3 = wv0*s_tt[4*lane+3] + wv1*s_tt[4*(lane+32)+3];
    #pragma unroll
    for (int o = 16; o; o >>= 1) {
        cgp0 += __shfl_xor_sync(0xffffffffu, cgp0, o);
        cgp1 += __shfl_xor_sync(0xffffffffu, cgp1, o);
        cgp2 += __shfl_xor_sync(0xffffffffu, cgp2, o);
        cgp3 += __shfl_xor_sync(0xffffffffu, cgp3, o);
    }
    if (lane == 0) {
        scg[warp][0] = cgp0; scg[warp][1] = cgp1;
        scg[warp][2] = cgp2; scg[warp][3] = cgp3;
    }
    __syncwarp();

    int rr = lane >> 3;
    const float* xp = xg + (size_t)p*(H*E) + lane*8;
    float a0=0.f,a1=0.f,a2=0.f,a3=0.f,a4=0.f,a5=0.f,a6=0.f,a7=0.f;
    #pragma unroll 4
    for (int e = 0; e < 64; e++) {
        float4 f0 = *(const float4*)(xp + e*256);
        float4 f1 = *(const float4*)(xp + e*256 + 4);
        float cc = scoef[warp][4*e + rr];
        a0 += cc*f0.x; a1 += cc*f0.y; a2 += cc*f0.z; a3 += cc*f0.w;
        a4 += cc*f1.x; a5 += cc*f1.y; a6 += cc*f1.z; a7 += cc*f1.w;
    }
    float b = scg[warp][rr];
    float4 o0, o1;
    o0.x = a0+b; o0.y = a1+b; o0.z = a2+b; o0.w = a3+b;
    o1.x = a4+b; o1.y = a5+b; o1.z = a6+b; o1.w = a7+b;
    *(float4*)&out[(size_t)p*H + lane*8]     = o0;
    *(float4*)&out[(size_t)p*H + lane*8 + 4] = o1;
}

// ---------------- launch ----------------
extern "C" void kernel_launch(void* const* d_in, const int* in_sizes, int n_in,
                              void* d_out, int out_size) {
    const float* th    = (const float*)d_in[0];
    const float* sh    = (const float*)d_in[1];
    const float* gamma = (const float*)d_in[2];
    const float* beta  = (const float*)d_in[3];
    const float* wt    = (const float*)d_in[4];
    const float* bt    = (const float*)d_in[5];
    const float* ws    = (const float*)d_in[6];
    const float* bs    = (const float*)d_in[7];
    float* out = (float*)d_out;

    size_t smem_tev = (size_t)(64*132 + 128*68 + 64 + 256) * sizeof(float);  // ~70 KB
    cudaFuncSetAttribute(k_tev, cudaFuncAttributeMaxDynamicSharedMemorySize, (int)smem_tev);

    k_init<<<1, 256>>>();
    k_tstats<<<256, 256>>>(th, gamma, beta, wt, bt);   // includes last-block prep
    k_tev<<<P/64, 512, smem_tev>>>(th, ws, bs);
    k_pass1<<<P/8, 256>>>(sh);                          // 4th launch -> profiled
    k_attn<<<256, 256>>>(gamma, beta);
    k_sm1<<<E*4, 256>>>();
    k_trn<<<P/64, 256>>>();
    k_out<<<P/8, 256>>>(sh, out);
}

// round 17
// speedup vs baseline: 1.2427x; 1.2427x over previous
#include <cuda_runtime.h>

#define P 16384
#define H 256
#define E 64
#define NA 64
#define PE (P*E)

// ---------------- static scratch ----------------
__device__ float g_tsum[H], g_tsumsq[H];     // temp BN sums
__device__ float g_ssum[H], g_ssumsq[H];     // spat BN sums
__device__ float g_w2T[H*NA];                // BN-folded temporal weights, transposed [h][a]
__device__ float g_cA[NA];                   // folded bias for te
__device__ float g_c[P];                     // c[p] = b_spat . te[p]
__device__ float g_v[P*H];                   // v[p,h]
__device__ float g_Vg[P*4];                  // group sums of v
__device__ float g_D[P*H];                   // raw dots
__device__ float g_ss[H], g_tt[H];           // spat BN scale/shift
__device__ float g_attnT[E*P];               // attn transposed [E][P]
__device__ float g_wv[P*E];                  // softmax weights [P][E]
__device__ float g_pmax[E*4], g_psum[E*4];   // softmax partials (4 chunks per e)

// ---------------- init: zero accumulators ----------------
__global__ void k_init() {
    int i = threadIdx.x;
    g_tsum[i] = 0.f; g_tsumsq[i] = 0.f; g_ssum[i] = 0.f; g_ssumsq[i] = 0.f;
    if (i < NA) g_cA[i] = 0.f;
}

// ---------------- temp_hidden per-column stats ----------------
__global__ void k_tstats(const float* __restrict__ th) {
    int c = threadIdx.x;
    float s = 0.f, s2 = 0.f;
    for (int p = blockIdx.x; p < P; p += gridDim.x) {
        float x = th[(size_t)p*H + c];
        s += x; s2 += x*x;
    }
    atomicAdd(&g_tsum[c], s);
    atomicAdd(&g_tsumsq[c], s2);
}

// ---------------- prep: fold BN into temporal weights (parallel, 64 blocks) ----------------
// w2T[h,a] = sc[h]*wt[a,h] ; cA[a] = bt[a] + sum_h sh[h]*wt[a,h]
__global__ void k_prep(const float* __restrict__ gamma,
                       const float* __restrict__ beta,
                       const float* __restrict__ wt,
                       const float* __restrict__ bt) {
    int hl = threadIdx.x >> 6;           // 0..3
    int a  = threadIdx.x & 63;
    int h  = blockIdx.x * 4 + hl;
    float m   = g_tsum[h]   * (1.0f/P);
    float var = g_tsumsq[h] * (1.0f/P) - m*m;
    float sc  = gamma[h] * rsqrtf(var + 1e-5f);
    float sh  = beta[h] - m*sc;
    float w   = wt[(size_t)a*H + h];
    g_w2T[h*NA + a] = sc * w;
    atomicAdd(&g_cA[a], sh * w);
    if (blockIdx.x == 0 && hl == 0) atomicAdd(&g_cA[a], bt[a]);
}

// ---------------- fused: te = th@w2^T + cA (smem) ; v = te@ws ; c, Vg ----------------
// 64 persons per block, 512 threads (measured 51.7us)
__global__ void __launch_bounds__(512) k_tev(const float* __restrict__ th,
                                             const float* __restrict__ ws,
                                             const float* __restrict__ bs) {
    extern __shared__ float sm[];
    float* s_a  = sm;                  // [64][132] th chunk; later s_te [64][68]
    float* s_w  = sm + 64*132;         // [128][68] w2T chunk; later s_ws [64][132]
    float* s_c  = s_w + 128*68;        // [64]
    float* s_vg = s_c + 64;            // [64][4]
    int tid = threadIdx.x;
    int pbase = blockIdx.x * 64;

    if (tid < 64)  s_c[tid] = 0.f;
    if (tid < 256) s_vg[tid] = 0.f;
    __syncthreads();

    // ---- GEMM1: te[64p][64a] = th[64p][256h] @ w2T ----
    int ty = tid >> 4, tx = tid & 15;            // 32x16 -> 2p x 4a tile
    float acc[2][4] = {};
    int c4  = (tid & 31) * 4, r0  = tid >> 5;    // stagers for 128-wide chunks
    int c4a = (tid & 15) * 4, r0w = tid >> 4;    // stager for s_w [128][64]

    for (int kc = 0; kc < 256; kc += 128) {
        #pragma unroll
        for (int r = r0; r < 64; r += 16)
            *(float4*)&s_a[r*132 + c4] = *(const float4*)&th[(size_t)(pbase + r)*H + kc + c4];
        #pragma unroll
        for (int r = r0w; r < 128; r += 32)
            *(float4*)&s_w[r*68 + c4a] = *(const float4*)&g_w2T[(size_t)(kc + r)*NA + c4a];
        __syncthreads();
        #pragma unroll 8
        for (int k = 0; k < 128; k++) {
            float a0 = s_a[(ty*2+0)*132 + k];
            float a1 = s_a[(ty*2+1)*132 + k];
            float4 b = *(float4*)&s_w[k*68 + tx*4];
            acc[0][0] += a0*b.x; acc[0][1] += a0*b.y; acc[0][2] += a0*b.z; acc[0][3] += a0*b.w;
            acc[1][0] += a1*b.x; acc[1][1] += a1*b.y; acc[1][2] += a1*b.z; acc[1][3] += a1*b.w;
        }
        __syncthreads();
    }

    // te epilogue: add cA, write into s_te (reuse s_a), accumulate c[p]
    float* s_te = s_a;                 // [64][68]
    {
        float4 cA4 = *(const float4*)&g_cA[tx*4];
        float4 bs4 = *(const float4*)&bs[tx*4];
        #pragma unroll
        for (int i = 0; i < 2; i++) {
            int pl = ty*2 + i;
            float t0 = acc[i][0] + cA4.x;
            float t1 = acc[i][1] + cA4.y;
            float t2 = acc[i][2] + cA4.z;
            float t3 = acc[i][3] + cA4.w;
            s_te[pl*68 + tx*4 + 0] = t0;
            s_te[pl*68 + tx*4 + 1] = t1;
            s_te[pl*68 + tx*4 + 2] = t2;
            s_te[pl*68 + tx*4 + 3] = t3;
            atomicAdd(&s_c[pl], t0*bs4.x + t1*bs4.y + t2*bs4.z + t3*bs4.w);
        }
    }
    __syncthreads();

    // ---- GEMM2: v[64p][256h] = te[64p][64a] @ ws[64a][256h] ----
    float* s_ws = s_w;                 // [64][132]
    int ty2 = tid >> 5, tx2 = tid & 31;     // 16x32 -> 4p x 4h tile per chunk
    for (int hc = 0; hc < 256; hc += 128) {
        #pragma unroll
        for (int r = r0; r < 64; r += 16)
            *(float4*)&s_ws[r*132 + c4] = *(const float4*)&ws[(size_t)r*H + hc + c4];
        __syncthreads();
        float a2c[4][4] = {};
        #pragma unroll 8
        for (int a = 0; a < 64; a++) {
            float4 w = *(float4*)&s_ws[a*132 + tx2*4];
            #pragma unroll
            for (int i = 0; i < 4; i++) {
                float t = s_te[(ty2*4+i)*68 + a];
                a2c[i][0] += t*w.x; a2c[i][1] += t*w.y; a2c[i][2] += t*w.z; a2c[i][3] += t*w.w;
            }
        }
        int g = (hc + tx2*4) >> 6;
        #pragma unroll
        for (int i = 0; i < 4; i++) {
            int pl = ty2*4 + i;
            float4 o;
            o.x = a2c[i][0]; o.y = a2c[i][1]; o.z = a2c[i][2]; o.w = a2c[i][3];
            __stcs((float4*)&g_v[(size_t)(pbase + pl)*H + hc + tx2*4], o);
            atomicAdd(&s_vg[pl*4 + g], o.x + o.y + o.z + o.w);
        }
        __syncthreads();
    }

    if (tid < 256) g_Vg[(size_t)pbase*4 + tid] = s_vg[tid];
    if (tid < 64)  g_c[pbase + tid] = s_c[tid];
}

// ---------------- fused big pass 1: D[p,ch] dots + spat BN stats ----------------
__global__ void __launch_bounds__(256) k_pass1(const float* __restrict__ xg) {
    __shared__ float s_sum[H], s_sq[H];
    __shared__ __align__(16) float s_D[8][256];
    int tid = threadIdx.x;
    s_sum[tid] = 0.f; s_sq[tid] = 0.f;
    __syncthreads();

    int warp = tid >> 5, lane = tid & 31;
    int p = blockIdx.x * 8 + warp;
    int rr = lane >> 3, seg = lane & 7;

    float vreg[8];
    const float* vp = &g_v[(size_t)p*H + lane*8];
    #pragma unroll
    for (int i = 0; i < 8; i++) vreg[i] = vp[i];

    const float* xp = xg + (size_t)p*(H*E) + lane*8;

    #pragma unroll 4
    for (int it = 0; it < 64; it++) {
        float4 a = __ldcs((const float4*)(xp + it*256));
        float4 b = __ldcs((const float4*)(xp + it*256 + 4));
        float dot = a.x*vreg[0] + a.y*vreg[1] + a.z*vreg[2] + a.w*vreg[3]
                  + b.x*vreg[4] + b.y*vreg[5] + b.z*vreg[6] + b.w*vreg[7];
        float s1 = a.x + a.y + a.z + a.w + b.x + b.y + b.z + b.w;
        float s2 = a.x*a.x + a.y*a.y + a.z*a.z + a.w*a.w
                 + b.x*b.x + b.y*b.y + b.z*b.z + b.w*b.w;
        #pragma unroll
        for (int o = 1; o < 8; o <<= 1) {
            dot += __shfl_xor_sync(0xffffffffu, dot, o);
            s1  += __shfl_xor_sync(0xffffffffu, s1,  o);
            s2  += __shfl_xor_sync(0xffffffffu, s2,  o);
        }
        if (seg == 0) {
            int ch = it*4 + rr;
            s_D[warp][ch] = dot;
            atomicAdd(&s_sum[ch], s1);
            atomicAdd(&s_sq[ch],  s2);
        }
    }
    __syncwarp();
    float4 d0 = *(float4*)&s_D[warp][lane*4];
    float4 d1 = *(float4*)&s_D[warp][128 + lane*4];
    __stcs((float4*)&g_D[(size_t)p*H + lane*4],       d0);
    __stcs((float4*)&g_D[(size_t)p*H + 128 + lane*4], d1);

    __syncthreads();
    atomicAdd(&g_ssum[tid],   s_sum[tid]);
    atomicAdd(&g_ssumsq[tid], s_sq[tid]);
}

// ---------------- attn scores (BN finalize folded in; 4-way e-split) ----------------
__global__ void __launch_bounds__(256) k_attn(const float* __restrict__ gamma,
                                              const float* __restrict__ beta) {
    __shared__ __align__(16) float ss[H];
    __shared__ __align__(16) float tt[H];
    int tid = threadIdx.x;
    {
        float inv = 1.0f / (float)PE;
        float m   = g_ssum[tid] * inv;
        float var = g_ssumsq[tid] * inv - m*m;
        float s   = gamma[tid] * rsqrtf(var + 1e-5f);
        ss[tid] = s;
        tt[tid] = beta[tid] - m*s;
        if (blockIdx.x == 0) { g_ss[tid] = s; g_tt[tid] = tt[tid]; }
    }
    __syncthreads();

    int pb = blockIdx.x & 63, ec = blockIdx.x >> 6;
    int p = pb*256 + tid;
    float vg0 = g_Vg[p*4+0], vg1 = g_Vg[p*4+1], vg2 = g_Vg[p*4+2], vg3 = g_Vg[p*4+3];
    float cp = g_c[p];
    const float4* Dp = (const float4*)&g_D[(size_t)p*H];
    const float T = 8.0f;   // E / sqrt(A)
    #pragma unroll
    for (int e = ec*16; e < ec*16 + 16; e++) {
        float4 d = __ldcs(&Dp[e]);
        float4 s = *(float4*)&ss[e*4];
        float4 t = *(float4*)&tt[e*4];
        float val = s.x*d.x + s.y*d.y + s.z*d.z + s.w*d.w
                  + t.x*vg0 + t.y*vg1 + t.z*vg2 + t.w*vg3 + cp;
        g_attnT[(size_t)e*P + p] = T * val;
    }
}

// ---------------- softmax stage 1: per-(e,chunk) max + sumexp ----------------
__global__ void __launch_bounds__(256) k_sm1() {
    __shared__ float red[32];
    __shared__ float bmax;
    int tid = threadIdx.x;
    const float* row = &g_attnT[(size_t)(blockIdx.x >> 2)*P + (blockIdx.x & 3)*4096];

    float mx = -1e30f;
    for (int i = tid; i < 4096; i += 256) mx = fmaxf(mx, row[i]);
    #pragma unroll
    for (int o = 16; o; o >>= 1) mx = fmaxf(mx, __shfl_xor_sync(0xffffffffu, mx, o));
    if ((tid & 31) == 0) red[tid >> 5] = mx;
    __syncthreads();
    if (tid < 32) {
        float v = (tid < 8) ? red[tid] : -1e30f;
        #pragma unroll
        for (int o = 4; o; o >>= 1) v = fmaxf(v, __shfl_xor_sync(0xffffffffu, v, o));
        if (tid == 0) bmax = v;
    }
    __syncthreads();
    float m = bmax;

    float s = 0.f;
    for (int i = tid; i < 4096; i += 256) s += expf(row[i] - m);
    #pragma unroll
    for (int o = 16; o; o >>= 1) s += __shfl_xor_sync(0xffffffffu, s, o);
    if ((tid & 31) == 0) red[tid >> 5] = s;
    __syncthreads();
    if (tid < 32) {
        float v = (tid < 8) ? red[tid] : 0.f;
        #pragma unroll
        for (int o = 4; o; o >>= 1) v += __shfl_xor_sync(0xffffffffu, v, o);
        if (tid == 0) { g_pmax[blockIdx.x] = m; g_psum[blockIdx.x] = v; }
    }
}

// ---------------- normalize + transpose: wv[p][e] = exp(attnT-M)*invS ----------------
__global__ void __launch_bounds__(256) k_trn() {
    __shared__ float sM[64], sInv[64];
    __shared__ float stile[64][65];
    int p0 = blockIdx.x * 64, tid = threadIdx.x;
    if (tid < 64) {
        float m0 = g_pmax[tid*4+0], m1 = g_pmax[tid*4+1];
        float m2 = g_pmax[tid*4+2], m3 = g_pmax[tid*4+3];
        float M = fmaxf(fmaxf(m0, m1), fmaxf(m2, m3));
        float S = g_psum[tid*4+0]*expf(m0-M) + g_psum[tid*4+1]*expf(m1-M)
                + g_psum[tid*4+2]*expf(m2-M) + g_psum[tid*4+3]*expf(m3-M);
        sM[tid] = M; sInv[tid] = 1.0f / S;
    }
    __syncthreads();
    int er = tid >> 6, pc = tid & 63;
    #pragma unroll
    for (int ee = 0; ee < 64; ee += 4) {
        float a = g_attnT[(size_t)(ee + er)*P + p0 + pc];
        stile[ee + er][pc] = expf(a - sM[ee + er]) * sInv[ee + er];
    }
    __syncthreads();
    int pr = tid >> 6, ec = tid & 63;
    #pragma unroll
    for (int pp = 0; pp < 64; pp += 4)
        g_wv[(size_t)(p0 + pp + pr)*E + ec] = stile[ec][pp + pr];
}

// ---------------- final big pass 2: warp-per-person streaming ----------------
__global__ void __launch_bounds__(256) k_out(const float* __restrict__ xg,
                                             float* __restrict__ out) {
    __shared__ float s_ss[H], s_tt[H];
    __shared__ float scoef[8][260];
    __shared__ float scg[8][4];
    int tid = threadIdx.x, warp = tid >> 5, lane = tid & 31;
    s_ss[tid] = g_ss[tid];
    s_tt[tid] = g_tt[tid];
    __syncthreads();

    int p = blockIdx.x * 8 + warp;
    float wv0 = g_wv[(size_t)p*E + lane];
    float wv1 = g_wv[(size_t)p*E + 32 + lane];
    float cgp0 = 0.f, cgp1 = 0.f, cgp2 = 0.f, cgp3 = 0.f;
    #pragma unroll
    for (int g = 0; g < 4; g++) {
        scoef[warp][4*lane + g]      = wv0 * s_ss[4*lane + g];
        scoef[warp][4*(lane+32) + g] = wv1 * s_ss[4*(lane+32) + g];
    }
    cgp0 = wv0*s_tt[4*lane+0] + wv1*s_tt[4*(lane+32)+0];
    cgp1 = wv0*s_tt[4*lane+1] + wv1*s_tt[4*(lane+32)+1];
    cgp2 = wv0*s_tt[4*lane+2] + wv1*s_tt[4*(lane+32)+2];
    cgp3 = wv0*s_tt[4*lane+3] + wv1*s_tt[4*(lane+32)+3];
    #pragma unroll
    for (int o = 16; o; o >>= 1) {
        cgp0 += __shfl_xor_sync(0xffffffffu, cgp0, o);
        cgp1 += __shfl_xor_sync(0xffffffffu, cgp1, o);
        cgp2 += __shfl_xor_sync(0xffffffffu, cgp2, o);
        cgp3 += __shfl_xor_sync(0xffffffffu, cgp3, o);
    }
    if (lane == 0) {
        scg[warp][0] = cgp0; scg[warp][1] = cgp1;
        scg[warp][2] = cgp2; scg[warp][3] = cgp3;
    }
    __syncwarp();

    int rr = lane >> 3;
    const float* xp = xg + (size_t)p*(H*E) + lane*8;
    float a0=0.f,a1=0.f,a2=0.f,a3=0.f,a4=0.f,a5=0.f,a6=0.f,a7=0.f;
    #pragma unroll 4
    for (int e = 0; e < 64; e++) {
        float4 f0 = __ldcs((const float4*)(xp + e*256));
        float4 f1 = __ldcs((const float4*)(xp + e*256 + 4));
        float cc = scoef[warp][4*e + rr];
        a0 += cc*f0.x; a1 += cc*f0.y; a2 += cc*f0.z; a3 += cc*f0.w;
        a4 += cc*f1.x; a5 += cc*f1.y; a6 += cc*f1.z; a7 += cc*f1.w;
    }
    float b = scg[warp][rr];
    float4 o0, o1;
    o0.x = a0+b; o0.y = a1+b; o0.z = a2+b; o0.w = a3+b;
    o1.x = a4+b; o1.y = a5+b; o1.z = a6+b; o1.w = a7+b;
    __stcs((float4*)&out[(size_t)p*H + lane*8],     o0);
    __stcs((float4*)&out[(size_t)p*H + lane*8 + 4], o1);
}

// ---------------- launch ----------------
extern "C" void kernel_launch(void* const* d_in, const int* in_sizes, int n_in,
                              void* d_out, int out_size) {
    const float* th    = (const float*)d_in[0];
    const float* sh    = (const float*)d_in[1];
    const float* gamma = (const float*)d_in[2];
    const float* beta  = (const float*)d_in[3];
    const float* wt    = (const float*)d_in[4];
    const float* bt    = (const float*)d_in[5];
    const float* ws    = (const float*)d_in[6];
    const float* bs    = (const float*)d_in[7];
    float* out = (float*)d_out;

    size_t smem_tev = (size_t)(64*132 + 128*68 + 64 + 256) * sizeof(float);  // ~70 KB
    cudaFuncSetAttribute(k_tev, cudaFuncAttributeMaxDynamicSharedMemorySize, (int)smem_tev);

    k_init<<<1, 256>>>();
    k_tstats<<<512, 256>>>(th);
    k_prep<<<64, 256>>>(gamma, beta, wt, bt);
    k_tev<<<P/64, 512, smem_tev>>>(th, ws, bs);
    k_pass1<<<P/8, 256>>>(sh);
    k_attn<<<256, 256>>>(gamma, beta);
    k_sm1<<<E*4, 256>>>();
    k_trn<<<P/64, 256>>>();
    k_out<<<P/8, 256>>>(sh, out);
}